// round 6
// baseline (speedup 1.0000x reference)
#include <cuda_runtime.h>
#include <cuda_bf16.h>
#include <math.h>

// Problem constants
#define NB 2
#define EE 16
#define CC 16
#define VV (64*128*128)              // 1,048,576 voxels per batch

#define CHUNK1 2048
#define P1_GX (VV / CHUNK1)          // 512 chunks
#define P2_THREADS 256
#define P2_GX (VV / (P2_THREADS*4))  // 1024 blocks in x (one float4 per thread)

#define DELTA_VAR 0.5f
#define DELTA_DIST 1.5f

// Scratch (device globals; zero-initialized at load; finalize re-zeros them
// after consuming, so every kernel_launch call sees zeros -> deterministic).
__device__ float g_sums[NB][CC][EE];
__device__ float g_counts[NB][CC];
__device__ float g_var[NB][CC];

// ---------------------------------------------------------------------------
// Histogram kernel: per-cluster counts from t only (8.4 MB total, ~3us).
// Per-warp 2-slot per-lane-column smem accumulators: no atomics, short chains.
// Also warms L2 with t for pass1/pass2.
// ---------------------------------------------------------------------------
__global__ __launch_bounds__(256, 6)
void hist_kernel(const int* __restrict__ t) {
    __shared__ float cA[8][CC * 32];   // 16 KB
    __shared__ float cB[8][CC * 32];   // 16 KB

    const int n    = blockIdx.y;
    const int tid  = threadIdx.x;
    const int w    = tid >> 5;
    const int lane = tid & 31;

    for (int i = tid; i < 8 * CC * 32; i += 256) {
        (&cA[0][0])[i] = 0.0f;
        (&cB[0][0])[i] = 0.0f;
    }
    __syncthreads();

    float* A = cA[w];
    float* B = cB[w];

    // 128 blocks in x, 256 threads: 32768 threads; VV/4 int4s -> 8 per thread
    const int4* tp  = (const int4*)(t + (size_t)n * VV);
    int idx = blockIdx.x * 256 + tid;

    int4 lb = tp[idx];
    #pragma unroll
    for (int it = 0; it < 8; it++) {
        int4 nxt;
        if (it < 7) nxt = tp[idx + 32768];
        A[lb.x * 32 + lane] += 1.0f;
        B[lb.y * 32 + lane] += 1.0f;
        A[lb.z * 32 + lane] += 1.0f;
        B[lb.w * 32 + lane] += 1.0f;
        lb = nxt;
        idx += 32768;
    }
    __syncwarp();

    #pragma unroll
    for (int c = 0; c < CC; c++) {
        float v = A[c * 32 + lane] + B[c * 32 + lane];
        #pragma unroll
        for (int o = 16; o > 0; o >>= 1) v += __shfl_xor_sync(0xffffffffu, v, o);
        if (lane == 0) atomicAdd(&g_counts[n][c], v);
    }
}

// ---------------------------------------------------------------------------
// Pass 1: per-cluster sums. Block = (chunk of 2048 voxels) x (8 planes).
// 8 warps; warp w owns plane zg*8+w. Labels staged once in smem.
// Per warp TWO disjoint slot-split accumulator arrays (x,z -> A; y,w -> B):
// breaks the STS->LDS alias chain in half. Software-pipelined loads so the
// next LDG.128 is always in flight during the scatter chain.
// smem: 8KB labels + 16KB A + 16KB B = 40KB static.
// ---------------------------------------------------------------------------
__global__ __launch_bounds__(256, 4)
void pass1_kernel(const float* __restrict__ x, const int* __restrict__ t) {
    __shared__ int   labels[CHUNK1];     // 8 KB
    __shared__ float accA[8][CC * 32];   // 16 KB
    __shared__ float accB[8][CC * 32];   // 16 KB

    const int n     = blockIdx.y;
    const int zg    = blockIdx.z;        // plane group: 0 -> planes 0-7, 1 -> 8-15
    const int base  = blockIdx.x * CHUNK1;
    const int tid   = threadIdx.x;
    const int w     = tid >> 5;
    const int lane  = tid & 31;
    const int plane = zg * 8 + w;

    const int4* tp = (const int4*)(t + (size_t)n * VV + base);
    for (int i = tid; i < CHUNK1 / 4; i += 256) ((int4*)labels)[i] = tp[i];
    for (int i = tid; i < 8 * CC * 32; i += 256) {
        (&accA[0][0])[i] = 0.0f;
        (&accB[0][0])[i] = 0.0f;
    }
    __syncthreads();

    float* A = accA[w];
    float* B = accB[w];
    const float* xp = x + ((size_t)n * EE + plane) * VV + base;

    // 16 float4 iterations per lane, software-pipelined one ahead
    int i = lane * 4;
    float4 v  = *(const float4*)(xp + i);
    int4   lb = *(const int4*)(labels + i);
    #pragma unroll
    for (int it = 0; it < 16; it++) {
        float4 vn; int4 lbn;
        if (it < 15) {
            vn  = *(const float4*)(xp + i + 128);
            lbn = *(const int4*)(labels + i + 128);
        }
        A[lb.x * 32 + lane] += v.x;
        B[lb.y * 32 + lane] += v.y;
        A[lb.z * 32 + lane] += v.z;
        B[lb.w * 32 + lane] += v.w;
        v = vn; lb = lbn;
        i += 128;
    }
    __syncwarp();

    #pragma unroll
    for (int c = 0; c < CC; c++) {
        float s = A[c * 32 + lane] + B[c * 32 + lane];
        #pragma unroll
        for (int o = 16; o > 0; o >>= 1) s += __shfl_xor_sync(0xffffffffu, s, o);
        if (lane == 0) atomicAdd(&g_sums[n][c][plane], s);
    }
}

// ---------------------------------------------------------------------------
// Pass 2: variance term. One float4 (4 voxels) per thread, one shot.
// 8 independent LDG.128 in flight per batch of planes (MLP=8).
// Means in smem, stride 20 floats (<=2-way conflict for random labels).
// Traversal REVERSED vs pass 1 so the tail of x (freshest in L2) is hit first.
// ---------------------------------------------------------------------------
__global__ __launch_bounds__(P2_THREADS, 4)
void pass2_kernel(const float* __restrict__ x, const int* __restrict__ t) {
    __shared__ float means_s[CC * 20];      // padded stride 20
    __shared__ float vacc[8][CC * 32];      // 16 KB (8 warps)
    __shared__ float wpart[8][CC];

    const int n    = blockIdx.y;
    const int tid  = threadIdx.x;
    const int w    = tid >> 5;
    const int lane = tid & 31;

    if (tid < CC * EE) {
        int c = tid >> 4, e = tid & 15;
        means_s[c * 20 + e] = g_sums[n][c][e] / g_counts[n][c];
    }
    for (int i = tid; i < 8 * CC * 32; i += P2_THREADS) (&vacc[0][0])[i] = 0.0f;
    __syncthreads();

    // reversed bijective index -> 4 consecutive voxels, warp stays contiguous
    const int idx = (P2_GX * P2_THREADS - 1) - (blockIdx.x * P2_THREADS + tid);
    const int v   = idx * 4;

    const float* xb = x + (size_t)n * EE * VV;
    const int4 lb = *(const int4*)(t + (size_t)n * VV + v);

    float ss0 = 0.0f, ss1 = 0.0f, ss2 = 0.0f, ss3 = 0.0f;
    #pragma unroll
    for (int eo = 0; eo < EE; eo += 8) {
        float4 xv[8];
        #pragma unroll
        for (int e = 0; e < 8; e++)
            xv[e] = *(const float4*)(xb + (size_t)(eo + e) * VV + v);
        #pragma unroll
        for (int e = 0; e < 8; e++) {
            const int ee = eo + e;
            float d;
            d = xv[e].x - means_s[lb.x * 20 + ee]; ss0 = fmaf(d, d, ss0);
            d = xv[e].y - means_s[lb.y * 20 + ee]; ss1 = fmaf(d, d, ss1);
            d = xv[e].z - means_s[lb.z * 20 + ee]; ss2 = fmaf(d, d, ss2);
            d = xv[e].w - means_s[lb.w * 20 + ee]; ss3 = fmaf(d, d, ss3);
        }
    }

    float* myv = vacc[w];
    float h;
    h = fmaxf(sqrtf(ss0) - DELTA_VAR, 0.0f); myv[lb.x * 32 + lane] += h * h;
    h = fmaxf(sqrtf(ss1) - DELTA_VAR, 0.0f); myv[lb.y * 32 + lane] += h * h;
    h = fmaxf(sqrtf(ss2) - DELTA_VAR, 0.0f); myv[lb.z * 32 + lane] += h * h;
    h = fmaxf(sqrtf(ss3) - DELTA_VAR, 0.0f); myv[lb.w * 32 + lane] += h * h;
    __syncwarp();

    #pragma unroll
    for (int c = 0; c < CC; c++) {
        float vv = myv[c * 32 + lane];
        #pragma unroll
        for (int o = 16; o > 0; o >>= 1) vv += __shfl_xor_sync(0xffffffffu, vv, o);
        if (lane == 0) wpart[w][c] = vv;
    }
    __syncthreads();

    if (tid < CC) {
        float s = 0.0f;
        #pragma unroll
        for (int ww = 0; ww < 8; ww++) s += wpart[ww][tid];
        atomicAdd(&g_var[n][tid], s);
    }
}

// ---------------------------------------------------------------------------
// Finalize: tiny. Computes loss, then RE-ZEROS the scratch globals so the
// next call (graph replay) starts clean without a separate init kernel.
// ---------------------------------------------------------------------------
__global__ void finalize_kernel(float* __restrict__ out) {
    __shared__ float means_s[NB][CC][EE];
    __shared__ float acc[NB][3];   // [n][0]=var, [1]=dist, [2]=reg

    const int tid = threadIdx.x;
    if (tid < NB * 3) (&acc[0][0])[tid] = 0.0f;
    if (tid < NB * CC * EE) {
        int n = tid >> 8, c = (tid >> 4) & 15, e = tid & 15;
        means_s[n][c][e] = g_sums[n][c][e] / g_counts[n][c];
    }
    __syncthreads();

    if (tid < NB * CC) {   // variance + regularizer terms
        int n = tid >> 4, c = tid & 15;
        atomicAdd(&acc[n][0], g_var[n][c] / g_counts[n][c]);
        float s = 0.0f;
        #pragma unroll
        for (int e = 0; e < EE; e++) {
            float m = means_s[n][c][e];
            s = fmaf(m, m, s);
        }
        atomicAdd(&acc[n][2], sqrtf(s));
    }

    {   // all-pairs hinged repulsion: tid encodes (n, a, b)
        int n = tid >> 8, a = (tid >> 4) & 15, b = tid & 15;
        float s = 0.0f;
        #pragma unroll
        for (int e = 0; e < EE; e++) {
            float d = means_s[n][a][e] - means_s[n][b][e];
            s = fmaf(d, d, s);
        }
        float dmat = sqrtf(s);
        float rep  = (a == b) ? 0.0f : (2.0f * DELTA_DIST);
        float h    = fmaxf(rep - dmat, 0.0f);
        atomicAdd(&acc[n][1], h * h);
    }
    __syncthreads();

    if (tid == 0) {
        float loss = 0.0f;
        #pragma unroll
        for (int n = 0; n < NB; n++) {
            float var_term  = acc[n][0] / (float)CC;
            float dist_term = acc[n][1] / (float)(CC * (CC - 1));
            float reg_term  = acc[n][2] / (float)CC;
            loss += var_term + dist_term + 0.001f * reg_term;
        }
        out[0] = loss / (float)NB;
    }
    __syncthreads();

    // re-zero scratch for the next invocation (all reads above are done)
    {
        float* s = &g_sums[0][0][0];
        for (int i = tid; i < NB * CC * EE; i += blockDim.x) s[i] = 0.0f;
        float* c = &g_counts[0][0];
        for (int i = tid; i < NB * CC; i += blockDim.x) c[i] = 0.0f;
        float* vv = &g_var[0][0];
        for (int i = tid; i < NB * CC; i += blockDim.x) vv[i] = 0.0f;
    }
}

// ---------------------------------------------------------------------------
extern "C" void kernel_launch(void* const* d_in, const int* in_sizes, int n_in,
                              void* d_out, int out_size) {
    const float* x = (const float*)d_in[0];   // [2,16,64,128,128] f32
    const int*   t = (const int*)d_in[1];     // [2,64,128,128]    i32
    float* out = (float*)d_out;

    hist_kernel <<<dim3(128, NB), 256>>>(t);
    pass1_kernel<<<dim3(P1_GX, NB, 2), 256>>>(x, t);
    pass2_kernel<<<dim3(P2_GX, NB), P2_THREADS>>>(x, t);
    finalize_kernel<<<1, 512>>>(out);
}

// round 7
// speedup vs baseline: 1.1235x; 1.1235x over previous
#include <cuda_runtime.h>
#include <cuda_bf16.h>
#include <math.h>

// Problem constants
#define NB 2
#define EE 16
#define CC 16
#define VV (64*128*128)              // 1,048,576 voxels per batch

#define CHUNK1 2048
#define P1_GX (VV / CHUNK1)          // 512 chunks
#define P2_THREADS 256
#define P2_GX (VV / (P2_THREADS*4))  // 1024 blocks in x (one float4 per thread)
#define P2_TOTAL (P2_GX * NB)        // total pass2 blocks (ticket target)

#define DELTA_VAR 0.5f
#define DELTA_DIST 1.5f

// Scratch (device globals; zero-initialized at load; the fused finalize
// re-zeros them after consuming, so every call sees zeros -> deterministic).
__device__ float g_sums[NB][CC][EE];
__device__ float g_counts[NB][CC];
__device__ float g_var[NB][CC];
__device__ unsigned int g_ticket;

// ---------------------------------------------------------------------------
// Pass 1: per-cluster sums + counts.
// Block = chunk of 2048 voxels; 8 warps; warp w owns planes w and w+8 as two
// DISJOINT slot arrays (independent RMW chains, 2 LDG.128 streams in flight).
// Labels staged once per chunk. Warp 0 additionally accumulates counts into a
// third disjoint array. Per-lane smem columns -> bank==lane, conflict-free.
// Software-pipelined with peeled last iteration.
// smem: 8KB labels + 16KB A + 16KB B + 2KB C = 42KB static.
// ---------------------------------------------------------------------------
__global__ __launch_bounds__(256)
void pass1_kernel(const float* __restrict__ x, const int* __restrict__ t) {
    __shared__ int   labels[CHUNK1];     // 8 KB
    __shared__ float accA[8][CC * 32];   // 16 KB  (plane w)
    __shared__ float accB[8][CC * 32];   // 16 KB  (plane w+8)
    __shared__ float accC[CC * 32];      // 2 KB   (counts, warp 0)

    const int n    = blockIdx.y;
    const int base = blockIdx.x * CHUNK1;
    const int tid  = threadIdx.x;
    const int w    = tid >> 5;
    const int lane = tid & 31;

    const int4* tp = (const int4*)(t + (size_t)n * VV + base);
    for (int i = tid; i < CHUNK1 / 4; i += 256) ((int4*)labels)[i] = tp[i];
    for (int i = tid; i < 8 * CC * 32; i += 256) {
        (&accA[0][0])[i] = 0.0f;
        (&accB[0][0])[i] = 0.0f;
    }
    for (int i = tid; i < CC * 32; i += 256) accC[i] = 0.0f;
    __syncthreads();

    float* A = accA[w];
    float* B = accB[w];
    const float* xpA = x + ((size_t)n * EE + w    ) * VV + base;
    const float* xpB = x + ((size_t)n * EE + w + 8) * VV + base;

    int i = lane * 4;
    float4 va = *(const float4*)(xpA + i);
    float4 vb = *(const float4*)(xpB + i);
    int4   lb = *(const int4*)(labels + i);

    if (w == 0) {
        #pragma unroll
        for (int it = 0; it < 15; it++) {
            float4 van = *(const float4*)(xpA + i + 128);
            float4 vbn = *(const float4*)(xpB + i + 128);
            int4   lbn = *(const int4*)(labels + i + 128);
            A[lb.x * 32 + lane] += va.x;  B[lb.x * 32 + lane] += vb.x;  accC[lb.x * 32 + lane] += 1.0f;
            A[lb.y * 32 + lane] += va.y;  B[lb.y * 32 + lane] += vb.y;  accC[lb.y * 32 + lane] += 1.0f;
            A[lb.z * 32 + lane] += va.z;  B[lb.z * 32 + lane] += vb.z;  accC[lb.z * 32 + lane] += 1.0f;
            A[lb.w * 32 + lane] += va.w;  B[lb.w * 32 + lane] += vb.w;  accC[lb.w * 32 + lane] += 1.0f;
            va = van; vb = vbn; lb = lbn; i += 128;
        }
        A[lb.x * 32 + lane] += va.x;  B[lb.x * 32 + lane] += vb.x;  accC[lb.x * 32 + lane] += 1.0f;
        A[lb.y * 32 + lane] += va.y;  B[lb.y * 32 + lane] += vb.y;  accC[lb.y * 32 + lane] += 1.0f;
        A[lb.z * 32 + lane] += va.z;  B[lb.z * 32 + lane] += vb.z;  accC[lb.z * 32 + lane] += 1.0f;
        A[lb.w * 32 + lane] += va.w;  B[lb.w * 32 + lane] += vb.w;  accC[lb.w * 32 + lane] += 1.0f;
    } else {
        #pragma unroll
        for (int it = 0; it < 15; it++) {
            float4 van = *(const float4*)(xpA + i + 128);
            float4 vbn = *(const float4*)(xpB + i + 128);
            int4   lbn = *(const int4*)(labels + i + 128);
            A[lb.x * 32 + lane] += va.x;  B[lb.x * 32 + lane] += vb.x;
            A[lb.y * 32 + lane] += va.y;  B[lb.y * 32 + lane] += vb.y;
            A[lb.z * 32 + lane] += va.z;  B[lb.z * 32 + lane] += vb.z;
            A[lb.w * 32 + lane] += va.w;  B[lb.w * 32 + lane] += vb.w;
            va = van; vb = vbn; lb = lbn; i += 128;
        }
        A[lb.x * 32 + lane] += va.x;  B[lb.x * 32 + lane] += vb.x;
        A[lb.y * 32 + lane] += va.y;  B[lb.y * 32 + lane] += vb.y;
        A[lb.z * 32 + lane] += va.z;  B[lb.z * 32 + lane] += vb.z;
        A[lb.w * 32 + lane] += va.w;  B[lb.w * 32 + lane] += vb.w;
    }
    __syncwarp();

    #pragma unroll
    for (int c = 0; c < CC; c++) {
        float sA = A[c * 32 + lane];
        float sB = B[c * 32 + lane];
        #pragma unroll
        for (int o = 16; o > 0; o >>= 1) {
            sA += __shfl_xor_sync(0xffffffffu, sA, o);
            sB += __shfl_xor_sync(0xffffffffu, sB, o);
        }
        if (lane == 0) {
            atomicAdd(&g_sums[n][c][w],     sA);
            atomicAdd(&g_sums[n][c][w + 8], sB);
        }
        if (w == 0) {
            float sC = accC[c * 32 + lane];
            #pragma unroll
            for (int o = 16; o > 0; o >>= 1) sC += __shfl_xor_sync(0xffffffffu, sC, o);
            if (lane == 0) atomicAdd(&g_counts[n][c], sC);
        }
    }
}

// ---------------------------------------------------------------------------
// Pass 2: variance term, with finalize FUSED into the last-finishing block
// (ticket pattern) to kill the standalone finalize launch.
// One float4 (4 voxels) per thread; 8 LDG.128 in flight per plane batch.
// Means in smem (stride 20). Traversal reversed vs pass 1 for L2 reuse.
// ---------------------------------------------------------------------------
__global__ __launch_bounds__(P2_THREADS)
void pass2_kernel(const float* __restrict__ x, const int* __restrict__ t,
                  float* __restrict__ out) {
    __shared__ float means_s[CC * 20];      // padded stride 20
    __shared__ float vacc[8][CC * 32];      // 16 KB (8 warps)
    __shared__ float wpart[8][CC];
    __shared__ unsigned int s_ticket;

    const int n    = blockIdx.y;
    const int tid  = threadIdx.x;
    const int w    = tid >> 5;
    const int lane = tid & 31;

    if (tid < CC * EE) {
        int c = tid >> 4, e = tid & 15;
        means_s[c * 20 + e] = g_sums[n][c][e] / g_counts[n][c];
    }
    for (int i = tid; i < 8 * CC * 32; i += P2_THREADS) (&vacc[0][0])[i] = 0.0f;
    __syncthreads();

    // reversed bijective index -> 4 consecutive voxels, warp stays contiguous
    const int idx = (P2_GX * P2_THREADS - 1) - (blockIdx.x * P2_THREADS + tid);
    const int v   = idx * 4;

    const float* xb = x + (size_t)n * EE * VV;
    const int4 lb = *(const int4*)(t + (size_t)n * VV + v);

    float ss0 = 0.0f, ss1 = 0.0f, ss2 = 0.0f, ss3 = 0.0f;
    #pragma unroll
    for (int eo = 0; eo < EE; eo += 8) {
        float4 xv[8];
        #pragma unroll
        for (int e = 0; e < 8; e++)
            xv[e] = *(const float4*)(xb + (size_t)(eo + e) * VV + v);
        #pragma unroll
        for (int e = 0; e < 8; e++) {
            const int ee = eo + e;
            float d;
            d = xv[e].x - means_s[lb.x * 20 + ee]; ss0 = fmaf(d, d, ss0);
            d = xv[e].y - means_s[lb.y * 20 + ee]; ss1 = fmaf(d, d, ss1);
            d = xv[e].z - means_s[lb.z * 20 + ee]; ss2 = fmaf(d, d, ss2);
            d = xv[e].w - means_s[lb.w * 20 + ee]; ss3 = fmaf(d, d, ss3);
        }
    }

    float* myv = vacc[w];
    float h;
    h = fmaxf(sqrtf(ss0) - DELTA_VAR, 0.0f); myv[lb.x * 32 + lane] += h * h;
    h = fmaxf(sqrtf(ss1) - DELTA_VAR, 0.0f); myv[lb.y * 32 + lane] += h * h;
    h = fmaxf(sqrtf(ss2) - DELTA_VAR, 0.0f); myv[lb.z * 32 + lane] += h * h;
    h = fmaxf(sqrtf(ss3) - DELTA_VAR, 0.0f); myv[lb.w * 32 + lane] += h * h;
    __syncwarp();

    #pragma unroll
    for (int c = 0; c < CC; c++) {
        float vv = myv[c * 32 + lane];
        #pragma unroll
        for (int o = 16; o > 0; o >>= 1) vv += __shfl_xor_sync(0xffffffffu, vv, o);
        if (lane == 0) wpart[w][c] = vv;
    }
    __syncthreads();

    if (tid < CC) {
        float s = 0.0f;
        #pragma unroll
        for (int ww = 0; ww < 8; ww++) s += wpart[ww][tid];
        atomicAdd(&g_var[n][tid], s);
    }

    // ---- fused finalize: last block to finish does the tiny epilogue ----
    __threadfence();
    if (tid == 0) s_ticket = atomicAdd(&g_ticket, 1u);
    __syncthreads();
    if (s_ticket != P2_TOTAL - 1) return;
    __threadfence();   // make all blocks' g_var/g_sums/g_counts visible

    __shared__ float means_f[NB][CC][EE];   // 2 KB
    __shared__ float accf[NB][3];           // [n][0]=var, [1]=dist, [2]=reg

    if (tid < NB * 3) (&accf[0][0])[tid] = 0.0f;
    for (int i = tid; i < NB * CC * EE; i += P2_THREADS) {
        int nn = i >> 8, c = (i >> 4) & 15, e = i & 15;
        means_f[nn][c][e] = g_sums[nn][c][e] / g_counts[nn][c];
    }
    __syncthreads();

    if (tid < NB * CC) {   // variance + regularizer terms
        int nn = tid >> 4, c = tid & 15;
        atomicAdd(&accf[nn][0], g_var[nn][c] / g_counts[nn][c]);
        float s = 0.0f;
        #pragma unroll
        for (int e = 0; e < EE; e++) {
            float m = means_f[nn][c][e];
            s = fmaf(m, m, s);
        }
        atomicAdd(&accf[nn][2], sqrtf(s));
    }

    for (int i = tid; i < NB * CC * CC; i += P2_THREADS) {  // all-pairs repulsion
        int nn = i >> 8, a = (i >> 4) & 15, b = i & 15;
        float s = 0.0f;
        #pragma unroll
        for (int e = 0; e < EE; e++) {
            float d = means_f[nn][a][e] - means_f[nn][b][e];
            s = fmaf(d, d, s);
        }
        float dmat = sqrtf(s);
        float rep  = (a == b) ? 0.0f : (2.0f * DELTA_DIST);
        float hh   = fmaxf(rep - dmat, 0.0f);
        atomicAdd(&accf[nn][1], hh * hh);
    }
    __syncthreads();

    if (tid == 0) {
        float loss = 0.0f;
        #pragma unroll
        for (int nn = 0; nn < NB; nn++) {
            float var_term  = accf[nn][0] / (float)CC;
            float dist_term = accf[nn][1] / (float)(CC * (CC - 1));
            float reg_term  = accf[nn][2] / (float)CC;
            loss += var_term + dist_term + 0.001f * reg_term;
        }
        out[0] = loss / (float)NB;
        g_ticket = 0u;
    }
    __syncthreads();

    // re-zero scratch for the next (graph-replay) invocation
    {
        float* s = &g_sums[0][0][0];
        for (int i = tid; i < NB * CC * EE; i += P2_THREADS) s[i] = 0.0f;
        float* c = &g_counts[0][0];
        for (int i = tid; i < NB * CC; i += P2_THREADS) c[i] = 0.0f;
        float* vv = &g_var[0][0];
        for (int i = tid; i < NB * CC; i += P2_THREADS) vv[i] = 0.0f;
    }
}

// ---------------------------------------------------------------------------
extern "C" void kernel_launch(void* const* d_in, const int* in_sizes, int n_in,
                              void* d_out, int out_size) {
    const float* x = (const float*)d_in[0];   // [2,16,64,128,128] f32
    const int*   t = (const int*)d_in[1];     // [2,64,128,128]    i32
    float* out = (float*)d_out;

    pass1_kernel<<<dim3(P1_GX, NB), 256>>>(x, t);
    pass2_kernel<<<dim3(P2_GX, NB), P2_THREADS>>>(x, t, out);
}